// round 4
// baseline (speedup 1.0000x reference)
#include <cuda_runtime.h>
#include <cstdint>

// ---------------------------------------------------------------------------
// Problem constants
//   B=128, T_V=64, T_A=128, E_V=1024, E_A=512, H=1024, EMB=512, C=512
//   IN=1024, VOCAB=20000
// Output = [logits(128*20000) | h_new(128*1024) | c_new(128*1024)]
// ---------------------------------------------------------------------------

// Scratch offsets (floats)
#define OFF_V2V     0u            // 8192*512
#define OFF_V2A     4194304u      // 16384*512
#define OFF_V1V     12582912u     // 128*512
#define OFF_V1A     12648448u     // 128*512
#define OFF_V1C     12713984u     // 128*512
#define OFF_CTXV    12779520u     // 128*1024
#define OFF_CTXA    12910592u     // 128*512
#define OFF_ALLCTX  12976128u     // 128*2*512
#define OFF_V2C     13107200u     // 256*512
#define OFF_X       13238272u     // 128*1024
#define OFF_GATES   13369344u     // 128*4096
#define OFF_H       13893632u     // 128*1024
#define SCRATCH_FLOATS 14024704u

__device__ float g_scratch[SCRATCH_FLOATS];

__device__ __forceinline__ uint32_t f2tf(float f) {
    uint32_t u;
    asm("cvt.rna.tf32.f32 %0, %1;" : "=r"(u) : "f"(f));
    return u;
}

// ---------------------------------------------------------------------------
// TF32 tensor-core GEMM core:  C[M,N] (+)= A[M,K] @ B[N,K]^T (+ bias[n])
// Tile 128x128x32, 256 threads = 8 warps (2 in M x 4 in N), warp tile 64x32.
// Requires M % 128 == 0, K % 32 == 0, lda/ldb % 4 == 0. N ragged-guarded.
// ---------------------------------------------------------------------------
__device__ __forceinline__ void gemm_core(
    const float* __restrict__ A, int lda,
    const float* __restrict__ B, int ldb,
    const float* __restrict__ bias,
    float* __restrict__ C, int ldc,
    int N, int K, int accum,
    int mBase, int nBase,
    uint32_t (*As)[36], uint32_t (*Bs)[36])
{
    const int tid  = threadIdx.x;
    const int lane = tid & 31;
    const int warp = tid >> 5;
    const int wm = warp >> 2;          // 0..1  (64-row slab)
    const int wn = warp & 3;           // 0..3  (32-col slab)

    const int lr = tid >> 3;           // 0..31  (load row base)
    const int lc = tid & 7;            // 0..7   (float4 column)

    float acc[4][4][4];
#pragma unroll
    for (int i = 0; i < 4; i++)
#pragma unroll
        for (int j = 0; j < 4; j++)
#pragma unroll
            for (int k = 0; k < 4; k++) acc[i][j][k] = 0.f;

    const int nk = K >> 5;
    float4 pa[4], pb[4];

    // ---- prefetch k-tile 0 ----
    {
        const float* Ap = A + (size_t)(mBase + lr) * lda + (lc << 2);
#pragma unroll
        for (int i = 0; i < 4; i++)
            pa[i] = *(const float4*)(Ap + (size_t)(i * 32) * lda);
#pragma unroll
        for (int i = 0; i < 4; i++) {
            const int nr = nBase + lr + i * 32;
            pb[i] = (nr < N) ? *(const float4*)(B + (size_t)nr * ldb + (lc << 2))
                             : make_float4(0.f, 0.f, 0.f, 0.f);
        }
    }
#pragma unroll
    for (int i = 0; i < 4; i++) {
        const int r = lr + (i << 5);
        uint4 v;
        v.x = f2tf(pa[i].x); v.y = f2tf(pa[i].y); v.z = f2tf(pa[i].z); v.w = f2tf(pa[i].w);
        *(uint4*)&As[r][lc << 2] = v;
        uint4 w;
        w.x = f2tf(pb[i].x); w.y = f2tf(pb[i].y); w.z = f2tf(pb[i].z); w.w = f2tf(pb[i].w);
        *(uint4*)&Bs[r][lc << 2] = w;
    }

    for (int kt = 0; kt < nk; kt++) {
        __syncthreads();

        const bool more = (kt + 1 < nk);
        if (more) {
            const int ko = (kt + 1) << 5;
            const float* Ap = A + (size_t)(mBase + lr) * lda + ko + (lc << 2);
#pragma unroll
            for (int i = 0; i < 4; i++)
                pa[i] = *(const float4*)(Ap + (size_t)(i * 32) * lda);
#pragma unroll
            for (int i = 0; i < 4; i++) {
                const int nr = nBase + lr + i * 32;
                pb[i] = (nr < N)
                    ? *(const float4*)(B + (size_t)nr * ldb + ko + (lc << 2))
                    : make_float4(0.f, 0.f, 0.f, 0.f);
            }
        }

#pragma unroll
        for (int kk = 0; kk < 32; kk += 8) {
            uint32_t a[4][4], b[4][2];
            const int c = kk + (lane & 3);
#pragma unroll
            for (int im = 0; im < 4; im++) {
                const int r = (wm << 6) + (im << 4) + (lane >> 2);
                a[im][0] = As[r][c];
                a[im][1] = As[r + 8][c];
                a[im][2] = As[r][c + 4];
                a[im][3] = As[r + 8][c + 4];
            }
#pragma unroll
            for (int jn = 0; jn < 4; jn++) {
                const int nr = (wn << 5) + (jn << 3) + (lane >> 2);
                b[jn][0] = Bs[nr][c];
                b[jn][1] = Bs[nr][c + 4];
            }
#pragma unroll
            for (int im = 0; im < 4; im++)
#pragma unroll
                for (int jn = 0; jn < 4; jn++)
                    asm volatile(
                        "mma.sync.aligned.m16n8k8.row.col.f32.tf32.tf32.f32 "
                        "{%0,%1,%2,%3}, {%4,%5,%6,%7}, {%8,%9}, {%0,%1,%2,%3};"
                        : "+f"(acc[im][jn][0]), "+f"(acc[im][jn][1]),
                          "+f"(acc[im][jn][2]), "+f"(acc[im][jn][3])
                        : "r"(a[im][0]), "r"(a[im][1]), "r"(a[im][2]), "r"(a[im][3]),
                          "r"(b[jn][0]), "r"(b[jn][1]));
        }

        __syncthreads();
        if (more) {
#pragma unroll
            for (int i = 0; i < 4; i++) {
                const int r = lr + (i << 5);
                uint4 v;
                v.x = f2tf(pa[i].x); v.y = f2tf(pa[i].y); v.z = f2tf(pa[i].z); v.w = f2tf(pa[i].w);
                *(uint4*)&As[r][lc << 2] = v;
                uint4 w;
                w.x = f2tf(pb[i].x); w.y = f2tf(pb[i].y); w.z = f2tf(pb[i].z); w.w = f2tf(pb[i].w);
                *(uint4*)&Bs[r][lc << 2] = w;
            }
        }
    }

    // ---- epilogue ----
#pragma unroll
    for (int im = 0; im < 4; im++) {
        const int m0 = mBase + (wm << 6) + (im << 4) + (lane >> 2);
#pragma unroll
        for (int jn = 0; jn < 4; jn++) {
            const int n0 = nBase + (wn << 5) + (jn << 3) + ((lane & 3) << 1);
#pragma unroll
            for (int half = 0; half < 2; half++) {
                const int m = m0 + half * 8;
                const float v0 = acc[im][jn][half * 2 + 0];
                const float v1 = acc[im][jn][half * 2 + 1];
                if (n0 < N) {
                    float xv = v0 + (bias ? bias[n0] : 0.f);
                    if (accum) C[(size_t)m * ldc + n0] += xv;
                    else       C[(size_t)m * ldc + n0]  = xv;
                }
                if (n0 + 1 < N) {
                    float xv = v1 + (bias ? bias[n0 + 1] : 0.f);
                    if (accum) C[(size_t)m * ldc + n0 + 1] += xv;
                    else       C[(size_t)m * ldc + n0 + 1]  = xv;
                }
            }
        }
    }
}

// ---------------------------------------------------------------------------
// Grouped GEMM: several independent GEMMs in one launch (flat grid,
// per-group block ranges via prefix-sum 'end').
// ---------------------------------------------------------------------------
struct GemmGroup {
    const float* A; const float* B; const float* bias; float* C;
    int lda, ldb, ldc, N, K, accum, nbx, end;
};
struct GemmList { GemmGroup g[6]; int n; };

__global__ void __launch_bounds__(256) gemm_grouped(GemmList L)
{
    __shared__ uint32_t As[128][36];
    __shared__ uint32_t Bs[128][36];

    const int bid = blockIdx.x;
    int gi = 0;
#pragma unroll
    for (int i = 0; i < 6; i++)
        if (i < L.n && bid >= L.g[i].end) gi = i + 1;
    const GemmGroup& G = L.g[gi];
    const int start = gi ? L.g[gi - 1].end : 0;
    const int lb = bid - start;
    const int by = lb / G.nbx;
    const int bx = lb - by * G.nbx;

    gemm_core(G.A, G.lda, G.B, G.ldb, G.bias, G.C, G.ldc,
              G.N, G.K, G.accum, by << 7, bx << 7, As, Bs);
}

// ---------------------------------------------------------------------------
// Both Bahdanau attentions in one launch: block 0..127 visual, 128..255 audio.
// ---------------------------------------------------------------------------
struct AttParams {
    const float* v1; const float* v2; const float* W3; const float* enc;
    float* ctx; int T, C, E;
};

__global__ void __launch_bounds__(256) attend_both(AttParams P0, AttParams P1)
{
    const AttParams P = (blockIdx.x >> 7) ? P1 : P0;
    const int b = blockIdx.x & 127;
    const int tid = threadIdx.x;
    const int warp = tid >> 5, lane = tid & 31;
    __shared__ float s_sc[128];
    __shared__ float s_inv;

    const int T = P.T, C = P.C, E = P.E;
    const float* v1b = P.v1 + (size_t)b * C;
    const float* v2b = P.v2 + (size_t)b * T * C;

    for (int t = warp; t < T; t += 8) {
        const float* row = v2b + (size_t)t * C;
        float acc = 0.f;
        for (int c = lane; c < C; c += 32)
            acc += tanhf(v1b[c] + row[c]) * P.W3[c];
#pragma unroll
        for (int o = 16; o; o >>= 1) acc += __shfl_xor_sync(0xffffffffu, acc, o);
        if (lane == 0) s_sc[t] = acc;
    }
    __syncthreads();

    if (tid == 0) {
        float m = -1e30f;
        for (int t = 0; t < T; t++) m = fmaxf(m, s_sc[t]);
        float s = 0.f;
        for (int t = 0; t < T; t++) { float e = expf(s_sc[t] - m); s_sc[t] = e; s += e; }
        s_inv = 1.f / s;
    }
    __syncthreads();
    const float inv = s_inv;

    const float* encb = P.enc + (size_t)b * T * E;
    for (int e = tid; e < E; e += 256) {
        float acc = 0.f;
        for (int t = 0; t < T; t++) acc += s_sc[t] * encb[(size_t)t * E + e];
        P.ctx[(size_t)b * E + e] = acc * inv;
    }
}

// ---------------------------------------------------------------------------
// Cross-modal attention (T=2) + final context + x = [input, tanh(final_ctx)]
// ---------------------------------------------------------------------------
__global__ void __launch_bounds__(256) ca_finish_kernel(
    const float* __restrict__ v1c,    // [B,512]
    const float* __restrict__ v2c,    // [B*2,512]
    const float* __restrict__ W3,     // [512]
    const float* __restrict__ allctx, // [B,2,512]
    const float* __restrict__ inp,    // [B,512]
    float* __restrict__ x)            // [B,1024]
{
    const int C = 512, EMB = 512;
    const int b = blockIdx.x;
    const int tid = threadIdx.x;
    const int warp = tid >> 5, lane = tid & 31;
    __shared__ float red0[8], red1[8];
    __shared__ float s_a0, s_a1;

    const float* v1b = v1c + (size_t)b * C;
    const float* v20 = v2c + (size_t)(2 * b) * C;
    const float* v21 = v20 + C;

    float p0 = 0.f, p1 = 0.f;
    for (int c = tid; c < C; c += 256) {
        const float w = W3[c];
        p0 += tanhf(v1b[c] + v20[c]) * w;
        p1 += tanhf(v1b[c] + v21[c]) * w;
    }
#pragma unroll
    for (int o = 16; o; o >>= 1) {
        p0 += __shfl_xor_sync(0xffffffffu, p0, o);
        p1 += __shfl_xor_sync(0xffffffffu, p1, o);
    }
    if (lane == 0) { red0[warp] = p0; red1[warp] = p1; }
    __syncthreads();
    if (tid == 0) {
        float s0 = 0.f, s1 = 0.f;
        for (int w = 0; w < 8; w++) { s0 += red0[w]; s1 += red1[w]; }
        const float m = fmaxf(s0, s1);
        const float e0 = expf(s0 - m), e1 = expf(s1 - m);
        const float inv = 1.f / (e0 + e1);
        s_a0 = e0 * inv; s_a1 = e1 * inv;
    }
    __syncthreads();
    const float a0 = s_a0, a1 = s_a1;

    const float* ctx0 = allctx + (size_t)b * 2 * C;
    const float* ctx1 = ctx0 + C;
    float* xb = x + (size_t)b * (EMB + C);
    const float* ib = inp + (size_t)b * EMB;
    for (int e = tid; e < EMB; e += 256) xb[e] = ib[e];
    for (int c = tid; c < C; c += 256)
        xb[EMB + c] = tanhf(a0 * ctx0[c] + a1 * ctx1[c]);
}

// ---------------------------------------------------------------------------
// LSTM pointwise: gates[B,4H] (+ biases) -> h_new, c_new
// ---------------------------------------------------------------------------
__global__ void __launch_bounds__(256) lstm_kernel(
    const float* __restrict__ gates,
    const float* __restrict__ b_ih, const float* __restrict__ b_hh,
    const float* __restrict__ c0,
    float* __restrict__ h_scratch,
    float* __restrict__ h_out, float* __restrict__ c_out)
{
    const int idx = blockIdx.x * 256 + threadIdx.x;
    const int b = idx >> 10, k = idx & 1023;
    const float* g = gates + (size_t)b * 4096;

    const float ig = g[k]        + b_ih[k]        + b_hh[k];
    const float fg = g[1024 + k] + b_ih[1024 + k] + b_hh[1024 + k];
    const float gg = g[2048 + k] + b_ih[2048 + k] + b_hh[2048 + k];
    const float og = g[3072 + k] + b_ih[3072 + k] + b_hh[3072 + k];

    const float si = 1.f / (1.f + expf(-ig));
    const float sf = 1.f / (1.f + expf(-fg));
    const float so = 1.f / (1.f + expf(-og));
    const float cn = sf * c0[idx] + si * tanhf(gg);
    const float hn = so * tanhf(cn);

    h_scratch[idx] = hn;
    h_out[idx] = hn;
    c_out[idx] = cn;
}

// ---------------------------------------------------------------------------
// Launch
// ---------------------------------------------------------------------------
static inline GemmGroup mkgrp(const float* A, int lda, const float* B, int ldb,
                              const float* bias, float* C, int ldc,
                              int M, int N, int K, int accum, int prevEnd)
{
    GemmGroup g;
    g.A = A; g.B = B; g.bias = bias; g.C = C;
    g.lda = lda; g.ldb = ldb; g.ldc = ldc;
    g.N = N; g.K = K; g.accum = accum;
    g.nbx = (N + 127) / 128;
    g.end = prevEnd + g.nbx * (M / 128);
    return g;
}

extern "C" void kernel_launch(void* const* d_in, const int* in_sizes, int n_in,
                              void* d_out, int out_size)
{
    (void)in_sizes; (void)n_in; (void)out_size;

    float* S = nullptr;
    cudaGetSymbolAddress((void**)&S, g_scratch);

    const float* input  = (const float*)d_in[0];
    const float* enc_v  = (const float*)d_in[1];
    const float* enc_a  = (const float*)d_in[2];
    const float* h0     = (const float*)d_in[3];
    const float* c0     = (const float*)d_in[4];
    const float* W_va1  = (const float*)d_in[5];
    const float* W_va2  = (const float*)d_in[6];
    const float* W_va3  = (const float*)d_in[7];
    const float* W_venc = (const float*)d_in[8];
    const float* W_aa1  = (const float*)d_in[9];
    const float* W_aa2  = (const float*)d_in[10];
    const float* W_aa3  = (const float*)d_in[11];
    const float* W_aenc = (const float*)d_in[12];
    const float* W_ca1  = (const float*)d_in[13];
    const float* W_ca2  = (const float*)d_in[14];
    const float* W_ca3  = (const float*)d_in[15];
    const float* W_ih   = (const float*)d_in[16];
    const float* W_hh   = (const float*)d_in[17];
    const float* b_ih   = (const float*)d_in[18];
    const float* b_hh   = (const float*)d_in[19];
    const float* W_out  = (const float*)d_in[20];
    const float* b_out  = (const float*)d_in[21];

    float* out    = (float*)d_out;
    float* logits = out;
    float* h_out  = out + 128 * 20000;
    float* c_out  = h_out + 128 * 1024;

    float* v2v    = S + OFF_V2V;
    float* v2a    = S + OFF_V2A;
    float* v1v    = S + OFF_V1V;
    float* v1a    = S + OFF_V1A;
    float* v1c    = S + OFF_V1C;
    float* ctxv   = S + OFF_CTXV;
    float* ctxa   = S + OFF_CTXA;
    float* allctx = S + OFF_ALLCTX;
    float* v2c    = S + OFF_V2C;
    float* x      = S + OFF_X;
    float* gates  = S + OFF_GATES;
    float* hsc    = S + OFF_H;

    // ---- launch 1: everything that depends only on inputs ----
    GemmList L1; L1.n = 6;
    L1.g[0] = mkgrp(enc_a, 512,  W_aa2, 512,  nullptr, v2a,   512,  16384, 512,  512,  0, 0);
    L1.g[1] = mkgrp(enc_v, 1024, W_va2, 1024, nullptr, v2v,   512,  8192,  512,  1024, 0, L1.g[0].end);
    L1.g[2] = mkgrp(h0,    1024, W_hh,  1024, nullptr, gates, 4096, 128,   4096, 1024, 0, L1.g[1].end);
    L1.g[3] = mkgrp(h0,    1024, W_va1, 1024, nullptr, v1v,   512,  128,   512,  1024, 0, L1.g[2].end);
    L1.g[4] = mkgrp(h0,    1024, W_aa1, 1024, nullptr, v1a,   512,  128,   512,  1024, 0, L1.g[3].end);
    L1.g[5] = mkgrp(h0,    1024, W_ca1, 1024, nullptr, v1c,   512,  128,   512,  1024, 0, L1.g[4].end);
    gemm_grouped<<<L1.g[5].end, 256>>>(L1);

    // ---- launch 2: both attentions ----
    AttParams Pv{v1v, v2v, W_va3, enc_v, ctxv, 64, 512, 1024};
    AttParams Pa{v1a, v2a, W_aa3, enc_a, ctxa, 128, 512, 512};
    attend_both<<<256, 256>>>(Pv, Pa);

    // ---- launch 3: vc/ac projections (interleaved into allctx[B,2,C]) ----
    GemmList L2; L2.n = 2;
    L2.g[0] = mkgrp(ctxv, 1024, W_venc, 1024, nullptr, allctx,       1024, 128, 512, 1024, 0, 0);
    L2.g[1] = mkgrp(ctxa, 512,  W_aenc, 512,  nullptr, allctx + 512, 1024, 128, 512, 512,  0, L2.g[0].end);
    gemm_grouped<<<L2.g[1].end, 256>>>(L2);

    // ---- launch 4: cross-modal v2 over stacked context rows ----
    GemmList L3; L3.n = 1;
    L3.g[0] = mkgrp(allctx, 512, W_ca2, 512, nullptr, v2c, 512, 256, 512, 512, 0, 0);
    gemm_grouped<<<L3.g[0].end, 256>>>(L3);

    // ---- launch 5: 2-way softmax + final context + x ----
    ca_finish_kernel<<<128, 256>>>(v1c, v2c, W_ca3, allctx, input, x);

    // ---- launch 6: x @ W_ih^T accumulated into gates ----
    GemmList L4; L4.n = 1;
    L4.g[0] = mkgrp(x, 1024, W_ih, 1024, nullptr, gates, 4096, 128, 4096, 1024, 1, 0);
    gemm_grouped<<<L4.g[0].end, 256>>>(L4);

    // ---- launch 7: LSTM pointwise ----
    lstm_kernel<<<512, 256>>>(gates, b_ih, b_hh, c0, hsc, h_out, c_out);

    // ---- launch 8: logits ----
    GemmList L5; L5.n = 1;
    L5.g[0] = mkgrp(hsc, 1024, W_out, 1024, b_out, logits, 20000, 128, 20000, 1024, 0, 0);
    gemm_grouped<<<L5.g[0].end, 256>>>(L5);
}

// round 5
// speedup vs baseline: 1.0807x; 1.0807x over previous
#include <cuda_runtime.h>
#include <cstdint>

// ---------------------------------------------------------------------------
// Problem constants
//   B=128, T_V=64, T_A=128, E_V=1024, E_A=512, H=1024, EMB=512, C=512
//   IN=1024, VOCAB=20000
// Output = [logits(128*20000) | h_new(128*1024) | c_new(128*1024)]
// ---------------------------------------------------------------------------

// Scratch offsets (floats)
#define OFF_V2V     0u            // 8192*512
#define OFF_V2A     4194304u      // 16384*512
#define OFF_V1V     12582912u     // 128*512
#define OFF_V1A     12648448u     // 128*512
#define OFF_V1C     12713984u     // 128*512
#define OFF_CTXV    12779520u     // 128*1024
#define OFF_CTXA    12910592u     // 128*512
#define OFF_ALLCTX  12976128u     // 128*2*512
#define OFF_V2C     13107200u     // 256*512
#define OFF_X       13238272u     // 128*1024
#define OFF_GATES   13369344u     // 128*4096
#define OFF_H       13893632u     // 128*1024
#define SCRATCH_FLOATS 14024704u

__device__ float g_scratch[SCRATCH_FLOATS];
__device__ int g_bar[8];   // monotonic barrier counters (never reset; replay-safe)

__device__ __forceinline__ uint32_t f2tf(float f) {
    uint32_t u;
    asm("cvt.rna.tf32.f32 %0, %1;" : "=r"(u) : "f"(f));
    return u;
}

// Grid-wide barrier for a co-resident grid of nblk blocks.
// Monotonic counter + generation goal: safe across CUDA-graph replays.
__device__ __forceinline__ void grid_bar(int i, int nblk) {
    __syncthreads();
    if (threadIdx.x == 0) {
        __threadfence();
        int old = atomicAdd(&g_bar[i], 1);
        int goal = (old / nblk + 1) * nblk;
        volatile int* p = &g_bar[i];
        while (*p < goal) { __nanosleep(64); }
        __threadfence();
    }
    __syncthreads();
}

// ---------------------------------------------------------------------------
// TF32 tensor-core GEMM core:  C[M,N] (+)= A[M,K] @ B[N,K]^T (+ bias[n])
// Tile 64x64x32, 128 threads = 4 warps (2x2), warp tile 32x32.
// Requires M % 64 == 0 (rows mBase..mBase+63 valid), K % 32 == 0,
// lda/ldb % 4 == 0. N ragged-guarded.
// ---------------------------------------------------------------------------
__device__ __forceinline__ void gemm_core(
    const float* __restrict__ A, int lda,
    const float* __restrict__ B, int ldb,
    const float* __restrict__ bias,
    float* __restrict__ C, int ldc,
    int N, int K, int accum,
    int mBase, int nBase,
    uint32_t (*As)[36], uint32_t (*Bs)[36])
{
    const int tid  = threadIdx.x;
    const int lane = tid & 31;
    const int warp = tid >> 5;
    const int wm = warp >> 1;
    const int wn = warp & 1;

    const int lr = tid >> 3;          // 0..15
    const int lc = tid & 7;           // 0..7 (float4 column)

    float acc[2][4][4];
#pragma unroll
    for (int i = 0; i < 2; i++)
#pragma unroll
        for (int j = 0; j < 4; j++)
#pragma unroll
            for (int k = 0; k < 4; k++) acc[i][j][k] = 0.f;

    const int nk = K >> 5;
    float4 pa[4], pb[4];

    {
        const float* Ap = A + (size_t)(mBase + lr) * lda + (lc << 2);
#pragma unroll
        for (int i = 0; i < 4; i++)
            pa[i] = *(const float4*)(Ap + (size_t)(i * 16) * lda);
#pragma unroll
        for (int i = 0; i < 4; i++) {
            const int nr = nBase + lr + i * 16;
            pb[i] = (nr < N) ? *(const float4*)(B + (size_t)nr * ldb + (lc << 2))
                             : make_float4(0.f, 0.f, 0.f, 0.f);
        }
    }
#pragma unroll
    for (int i = 0; i < 4; i++) {
        const int r = lr + (i << 4);
        uint4 v;
        v.x = f2tf(pa[i].x); v.y = f2tf(pa[i].y); v.z = f2tf(pa[i].z); v.w = f2tf(pa[i].w);
        *(uint4*)&As[r][lc << 2] = v;
        uint4 w;
        w.x = f2tf(pb[i].x); w.y = f2tf(pb[i].y); w.z = f2tf(pb[i].z); w.w = f2tf(pb[i].w);
        *(uint4*)&Bs[r][lc << 2] = w;
    }

    for (int kt = 0; kt < nk; kt++) {
        __syncthreads();

        const bool more = (kt + 1 < nk);
        if (more) {
            const int ko = (kt + 1) << 5;
            const float* Ap = A + (size_t)(mBase + lr) * lda + ko + (lc << 2);
#pragma unroll
            for (int i = 0; i < 4; i++)
                pa[i] = *(const float4*)(Ap + (size_t)(i * 16) * lda);
#pragma unroll
            for (int i = 0; i < 4; i++) {
                const int nr = nBase + lr + i * 16;
                pb[i] = (nr < N)
                    ? *(const float4*)(B + (size_t)nr * ldb + ko + (lc << 2))
                    : make_float4(0.f, 0.f, 0.f, 0.f);
            }
        }

#pragma unroll
        for (int kk = 0; kk < 32; kk += 8) {
            uint32_t a[2][4], b[4][2];
            const int c = kk + (lane & 3);
#pragma unroll
            for (int im = 0; im < 2; im++) {
                const int r = (wm << 5) + (im << 4) + (lane >> 2);
                a[im][0] = As[r][c];
                a[im][1] = As[r + 8][c];
                a[im][2] = As[r][c + 4];
                a[im][3] = As[r + 8][c + 4];
            }
#pragma unroll
            for (int jn = 0; jn < 4; jn++) {
                const int nr = (wn << 5) + (jn << 3) + (lane >> 2);
                b[jn][0] = Bs[nr][c];
                b[jn][1] = Bs[nr][c + 4];
            }
#pragma unroll
            for (int im = 0; im < 2; im++)
#pragma unroll
                for (int jn = 0; jn < 4; jn++)
                    asm volatile(
                        "mma.sync.aligned.m16n8k8.row.col.f32.tf32.tf32.f32 "
                        "{%0,%1,%2,%3}, {%4,%5,%6,%7}, {%8,%9}, {%0,%1,%2,%3};"
                        : "+f"(acc[im][jn][0]), "+f"(acc[im][jn][1]),
                          "+f"(acc[im][jn][2]), "+f"(acc[im][jn][3])
                        : "r"(a[im][0]), "r"(a[im][1]), "r"(a[im][2]), "r"(a[im][3]),
                          "r"(b[jn][0]), "r"(b[jn][1]));
        }

        __syncthreads();
        if (more) {
#pragma unroll
            for (int i = 0; i < 4; i++) {
                const int r = lr + (i << 4);
                uint4 v;
                v.x = f2tf(pa[i].x); v.y = f2tf(pa[i].y); v.z = f2tf(pa[i].z); v.w = f2tf(pa[i].w);
                *(uint4*)&As[r][lc << 2] = v;
                uint4 w;
                w.x = f2tf(pb[i].x); w.y = f2tf(pb[i].y); w.z = f2tf(pb[i].z); w.w = f2tf(pb[i].w);
                *(uint4*)&Bs[r][lc << 2] = w;
            }
        }
    }

#pragma unroll
    for (int im = 0; im < 2; im++) {
        const int m0 = mBase + (wm << 5) + (im << 4) + (lane >> 2);
#pragma unroll
        for (int jn = 0; jn < 4; jn++) {
            const int n0 = nBase + (wn << 5) + (jn << 3) + ((lane & 3) << 1);
#pragma unroll
            for (int half = 0; half < 2; half++) {
                const int m = m0 + half * 8;
                const float v0 = acc[im][jn][half * 2 + 0];
                const float v1 = acc[im][jn][half * 2 + 1];
                if (n0 < N) {
                    float xv = v0 + (bias ? bias[n0] : 0.f);
                    if (accum) C[(size_t)m * ldc + n0] += xv;
                    else       C[(size_t)m * ldc + n0]  = xv;
                }
                if (n0 + 1 < N) {
                    float xv = v1 + (bias ? bias[n0 + 1] : 0.f);
                    if (accum) C[(size_t)m * ldc + n0 + 1] += xv;
                    else       C[(size_t)m * ldc + n0 + 1]  = xv;
                }
            }
        }
    }
}

// ---------------------------------------------------------------------------
// Grouped GEMM launch wrapper (flat grid, prefix-sum block ranges).
// ---------------------------------------------------------------------------
struct GemmGroup {
    const float* A; const float* B; const float* bias; float* C;
    int lda, ldb, ldc, N, K, accum, nbx, end;
};
struct GemmList { GemmGroup g[6]; int n; };

__global__ void __launch_bounds__(128) gemm_grouped(GemmList L)
{
    __shared__ uint32_t As[64][36];
    __shared__ uint32_t Bs[64][36];

    const int bid = blockIdx.x;
    int gi = 0;
#pragma unroll
    for (int i = 0; i < 6; i++)
        if (i < L.n && bid >= L.g[i].end) gi = i + 1;
    const GemmGroup& G = L.g[gi];
    const int start = gi ? L.g[gi - 1].end : 0;
    const int lb = bid - start;
    const int by = lb / G.nbx;
    const int bx = lb - by * G.nbx;

    gemm_core(G.A, G.lda, G.B, G.ldb, G.bias, G.C, G.ldc,
              G.N, G.K, G.accum, by << 6, bx << 6, As, Bs);
}

// ---------------------------------------------------------------------------
// Both Bahdanau attentions in one launch: block 0..127 visual, 128..255 audio.
// ---------------------------------------------------------------------------
struct AttParams {
    const float* v1; const float* v2; const float* W3; const float* enc;
    float* ctx; int T, C, E;
};

__global__ void __launch_bounds__(256) attend_both(AttParams P0, AttParams P1)
{
    const AttParams P = (blockIdx.x >> 7) ? P1 : P0;
    const int b = blockIdx.x & 127;
    const int tid = threadIdx.x;
    const int warp = tid >> 5, lane = tid & 31;
    __shared__ float s_sc[128];
    __shared__ float s_inv;

    const int T = P.T, C = P.C, E = P.E;
    const float* v1b = P.v1 + (size_t)b * C;
    const float* v2b = P.v2 + (size_t)b * T * C;

    for (int t = warp; t < T; t += 8) {
        const float* row = v2b + (size_t)t * C;
        float acc = 0.f;
        for (int c = lane; c < C; c += 32)
            acc += tanhf(v1b[c] + row[c]) * P.W3[c];
#pragma unroll
        for (int o = 16; o; o >>= 1) acc += __shfl_xor_sync(0xffffffffu, acc, o);
        if (lane == 0) s_sc[t] = acc;
    }
    __syncthreads();

    if (tid == 0) {
        float m = -1e30f;
        for (int t = 0; t < T; t++) m = fmaxf(m, s_sc[t]);
        float s = 0.f;
        for (int t = 0; t < T; t++) { float e = expf(s_sc[t] - m); s_sc[t] = e; s += e; }
        s_inv = 1.f / s;
    }
    __syncthreads();
    const float inv = s_inv;

    const float* encb = P.enc + (size_t)b * T * E;
    for (int e = tid; e < E; e += 256) {
        float acc = 0.f;
        for (int t = 0; t < T; t++) acc += s_sc[t] * encb[(size_t)t * E + e];
        P.ctx[(size_t)b * E + e] = acc * inv;
    }
}

// ---------------------------------------------------------------------------
// Persistent fused chain: proj -> v2c -> ca_finish -> gih -> lstm
// Grid MUST be 128 blocks x 128 threads (all co-resident on 148 SMs).
// ---------------------------------------------------------------------------
struct ChainParams {
    const float* ctxv; const float* ctxa;
    const float* W_venc; const float* W_aenc; const float* W_ca2;
    const float* v1c; const float* W_ca3; const float* input; const float* W_ih;
    const float* b_ih; const float* b_hh; const float* c0;
    float* allctx; float* v2c; float* x; float* gates;
    float* hsc; float* h_out; float* c_out;
};

__global__ void __launch_bounds__(128) fused_chain(ChainParams P)
{
    __shared__ uint32_t As[64][36];
    __shared__ uint32_t Bs[64][36];
    __shared__ float red0[4], red1[4];
    __shared__ float s_a0, s_a1;

    const int bid = blockIdx.x;
    const int tid = threadIdx.x;

    // ---- P1: vc/ac projections into allctx[B,2,512] (32 tile tasks) ----
    if (bid < 32) {
        if (bid < 16) {
            gemm_core(P.ctxv, 1024, P.W_venc, 1024, nullptr, P.allctx, 1024,
                      512, 1024, 0, (bid >> 3) << 6, (bid & 7) << 6, As, Bs);
        } else {
            const int t = bid - 16;
            gemm_core(P.ctxa, 512, P.W_aenc, 512, nullptr, P.allctx + 512, 1024,
                      512, 512, 0, (t >> 3) << 6, (t & 7) << 6, As, Bs);
        }
    }
    grid_bar(0, 128);

    // ---- P2: v2c[256,512] = allctx @ W_ca2^T (32 tile tasks) ----
    if (bid < 32) {
        gemm_core(P.allctx, 512, P.W_ca2, 512, nullptr, P.v2c, 512,
                  512, 512, 0, (bid >> 3) << 6, (bid & 7) << 6, As, Bs);
    }
    grid_bar(1, 128);

    // ---- P3: per-batch 2-way softmax + final ctx + x = [input, tanh(ctx)] ----
    {
        const int b = bid;
        const int warp = tid >> 5, lane = tid & 31;
        const float* v1b = P.v1c + (size_t)b * 512;
        const float* v20 = P.v2c + (size_t)(2 * b) * 512;
        const float* v21 = v20 + 512;

        float p0 = 0.f, p1 = 0.f;
        for (int c = tid; c < 512; c += 128) {
            const float w = P.W_ca3[c];
            p0 += tanhf(v1b[c] + v20[c]) * w;
            p1 += tanhf(v1b[c] + v21[c]) * w;
        }
#pragma unroll
        for (int o = 16; o; o >>= 1) {
            p0 += __shfl_xor_sync(0xffffffffu, p0, o);
            p1 += __shfl_xor_sync(0xffffffffu, p1, o);
        }
        if (lane == 0) { red0[warp] = p0; red1[warp] = p1; }
        __syncthreads();
        if (tid == 0) {
            float s0 = red0[0] + red0[1] + red0[2] + red0[3];
            float s1 = red1[0] + red1[1] + red1[2] + red1[3];
            const float m = fmaxf(s0, s1);
            const float e0 = expf(s0 - m), e1 = expf(s1 - m);
            const float inv = 1.f / (e0 + e1);
            s_a0 = e0 * inv; s_a1 = e1 * inv;
        }
        __syncthreads();
        const float a0 = s_a0, a1 = s_a1;

        const float* ctx0 = P.allctx + (size_t)b * 1024;
        const float* ctx1 = ctx0 + 512;
        float* xb = P.x + (size_t)b * 1024;
        const float* ib = P.input + (size_t)b * 512;
        for (int e = tid; e < 512; e += 128) xb[e] = ib[e];
        for (int c = tid; c < 512; c += 128)
            xb[512 + c] = tanhf(a0 * ctx0[c] + a1 * ctx1[c]);
    }
    grid_bar(2, 128);

    // ---- P4: gates += x @ W_ih^T  (128 tile tasks: 2 x 64) ----
    {
        const int by = bid >> 6;        // 0..1
        const int bx = bid & 63;        // 0..63
        gemm_core(P.x, 1024, P.W_ih, 1024, nullptr, P.gates, 4096,
                  4096, 1024, 1, by << 6, bx << 6, As, Bs);
    }
    grid_bar(3, 128);

    // ---- P5: LSTM pointwise ----
    for (int idx = bid * 128 + tid; idx < 128 * 1024; idx += 128 * 128) {
        const int b = idx >> 10, k = idx & 1023;
        const float* g = P.gates + (size_t)b * 4096;
        const float ig = g[k]        + P.b_ih[k]        + P.b_hh[k];
        const float fg = g[1024 + k] + P.b_ih[1024 + k] + P.b_hh[1024 + k];
        const float gg = g[2048 + k] + P.b_ih[2048 + k] + P.b_hh[2048 + k];
        const float og = g[3072 + k] + P.b_ih[3072 + k] + P.b_hh[3072 + k];

        const float si = 1.f / (1.f + expf(-ig));
        const float sf = 1.f / (1.f + expf(-fg));
        const float so = 1.f / (1.f + expf(-og));
        const float cn = sf * P.c0[idx] + si * tanhf(gg);
        const float hn = so * tanhf(cn);

        P.hsc[idx] = hn;
        P.h_out[idx] = hn;
        P.c_out[idx] = cn;
    }
}

// ---------------------------------------------------------------------------
// Launch
// ---------------------------------------------------------------------------
static inline GemmGroup mkgrp(const float* A, int lda, const float* B, int ldb,
                              const float* bias, float* C, int ldc,
                              int M, int N, int K, int accum, int prevEnd)
{
    GemmGroup g;
    g.A = A; g.B = B; g.bias = bias; g.C = C;
    g.lda = lda; g.ldb = ldb; g.ldc = ldc;
    g.N = N; g.K = K; g.accum = accum;
    g.nbx = (N + 63) / 64;
    g.end = prevEnd + g.nbx * (M / 64);
    return g;
}

extern "C" void kernel_launch(void* const* d_in, const int* in_sizes, int n_in,
                              void* d_out, int out_size)
{
    (void)in_sizes; (void)n_in; (void)out_size;

    float* S = nullptr;
    cudaGetSymbolAddress((void**)&S, g_scratch);

    const float* input  = (const float*)d_in[0];
    const float* enc_v  = (const float*)d_in[1];
    const float* enc_a  = (const float*)d_in[2];
    const float* h0     = (const float*)d_in[3];
    const float* c0     = (const float*)d_in[4];
    const float* W_va1  = (const float*)d_in[5];
    const float* W_va2  = (const float*)d_in[6];
    const float* W_va3  = (const float*)d_in[7];
    const float* W_venc = (const float*)d_in[8];
    const float* W_aa1  = (const float*)d_in[9];
    const float* W_aa2  = (const float*)d_in[10];
    const float* W_aa3  = (const float*)d_in[11];
    const float* W_aenc = (const float*)d_in[12];
    const float* W_ca1  = (const float*)d_in[13];
    const float* W_ca2  = (const float*)d_in[14];
    const float* W_ca3  = (const float*)d_in[15];
    const float* W_ih   = (const float*)d_in[16];
    const float* W_hh   = (const float*)d_in[17];
    const float* b_ih   = (const float*)d_in[18];
    const float* b_hh   = (const float*)d_in[19];
    const float* W_out  = (const float*)d_in[20];
    const float* b_out  = (const float*)d_in[21];

    float* out    = (float*)d_out;
    float* logits = out;
    float* h_out  = out + 128 * 20000;
    float* c_out  = h_out + 128 * 1024;

    float* v2v    = S + OFF_V2V;
    float* v2a    = S + OFF_V2A;
    float* v1v    = S + OFF_V1V;
    float* v1a    = S + OFF_V1A;
    float* v1c    = S + OFF_V1C;
    float* ctxv   = S + OFF_CTXV;
    float* ctxa   = S + OFF_CTXA;
    float* allctx = S + OFF_ALLCTX;
    float* v2c    = S + OFF_V2C;
    float* x      = S + OFF_X;
    float* gates  = S + OFF_GATES;
    float* hsc    = S + OFF_H;

    // ---- launch 1: everything that depends only on inputs ----
    GemmList L1; L1.n = 6;
    L1.g[0] = mkgrp(enc_a, 512,  W_aa2, 512,  nullptr, v2a,   512,  16384, 512,  512,  0, 0);
    L1.g[1] = mkgrp(enc_v, 1024, W_va2, 1024, nullptr, v2v,   512,  8192,  512,  1024, 0, L1.g[0].end);
    L1.g[2] = mkgrp(h0,    1024, W_hh,  1024, nullptr, gates, 4096, 128,   4096, 1024, 0, L1.g[1].end);
    L1.g[3] = mkgrp(h0,    1024, W_va1, 1024, nullptr, v1v,   512,  128,   512,  1024, 0, L1.g[2].end);
    L1.g[4] = mkgrp(h0,    1024, W_aa1, 1024, nullptr, v1a,   512,  128,   512,  1024, 0, L1.g[3].end);
    L1.g[5] = mkgrp(h0,    1024, W_ca1, 1024, nullptr, v1c,   512,  128,   512,  1024, 0, L1.g[4].end);
    gemm_grouped<<<L1.g[5].end, 128>>>(L1);

    // ---- launch 2: both attentions ----
    AttParams Pv{v1v, v2v, W_va3, enc_v, ctxv, 64, 512, 1024};
    AttParams Pa{v1a, v2a, W_aa3, enc_a, ctxa, 128, 512, 512};
    attend_both<<<256, 256>>>(Pv, Pa);

    // ---- launch 3: persistent fused chain (proj -> v2c -> ca -> gih -> lstm) ----
    ChainParams CP;
    CP.ctxv = ctxv; CP.ctxa = ctxa;
    CP.W_venc = W_venc; CP.W_aenc = W_aenc; CP.W_ca2 = W_ca2;
    CP.v1c = v1c; CP.W_ca3 = W_ca3; CP.input = input; CP.W_ih = W_ih;
    CP.b_ih = b_ih; CP.b_hh = b_hh; CP.c0 = c0;
    CP.allctx = allctx; CP.v2c = v2c; CP.x = x; CP.gates = gates;
    CP.hsc = hsc; CP.h_out = h_out; CP.c_out = c_out;
    fused_chain<<<128, 128>>>(CP);

    // ---- launch 4: logits ----
    GemmList L5; L5.n = 1;
    L5.g[0] = mkgrp(hsc, 1024, W_out, 1024, b_out, logits, 20000, 128, 20000, 1024, 0, 0);
    gemm_grouped<<<L5.g[0].end, 128>>>(L5);
}